// round 11
// baseline (speedup 1.0000x reference)
#include <cuda_runtime.h>
#include <cstdint>

// ---------------- problem constants ----------------
constexpr int Bq   = 32;
constexpr int Tq   = 8192;
constexpr int Dq   = 64;
constexpr int SPAN = 512;       // timesteps per CTA (loss-accumulating region)
constexpr int WU   = 96;        // warm-up rows after the seed row (history = 97 rows)
constexpr int NSP  = Tq / SPAN; // 16 spans per batch row

struct Ema { float pe0, pe1, pe2, te0, te1, te2; };

// dp = x - pe has the same sign as pd = pe_new - pe_old = alpha*dp (alpha>0),
// so the sign-mismatch mask is a sign-bit XOR.
__device__ __forceinline__ void sstep_loss(float a, float x, float y,
                                           float& pe, float& te, float& acc) {
    float dp = x - pe;
    float dq = y - te;
    pe = fmaf(a, dp, pe);
    te = fmaf(a, dq, te);
    float df = pe - te;
    float d2 = df * df;
    int m = (__float_as_int(dp) ^ __float_as_int(dq)) >> 31;   // all-ones iff mismatch
    acc += __int_as_float(m & __float_as_int(d2));
}

__device__ __forceinline__ void sstep_warm(float a, float x, float y,
                                           float& pe, float& te) {
    pe = fmaf(a, x - pe, pe);
    te = fmaf(a, y - te, te);
}

// Load 8 rows at a compile-time row offset (immediate-offset LDG.32s).
__device__ __forceinline__ void load8o(const float* pp, const float* qq, int rofs,
                                       float* P, float* Q) {
    #pragma unroll
    for (int u = 0; u < 8; ++u) {
        P[u] = pp[(rofs + u) * Dq];
        Q[u] = qq[(rofs + u) * Dq];
    }
}

__device__ __forceinline__ void warm8(const float* P, const float* Q, Ema& s) {
    #pragma unroll
    for (int u = 0; u < 8; ++u) {
        sstep_warm(0.1f, P[u], Q[u], s.pe0, s.te0);
        sstep_warm(0.3f, P[u], Q[u], s.pe1, s.te1);
        sstep_warm(0.5f, P[u], Q[u], s.pe2, s.te2);
    }
}

__device__ __forceinline__ void loss8(const float* P, const float* Q, Ema& s,
                                      float& a0, float& a1, float& a2) {
    #pragma unroll
    for (int u = 0; u < 8; ++u) {
        sstep_loss(0.1f, P[u], Q[u], s.pe0, s.te0, a0);
        sstep_loss(0.3f, P[u], Q[u], s.pe1, s.te1, a1);
        sstep_loss(0.5f, P[u], Q[u], s.pe2, s.te2, a2);
    }
}

__global__ void zero_out_kernel(float* out) { out[0] = 0.0f; }

// 512 CTAs of 64 threads (2 warps) -> 1024 warps chip-wide, single wave.
// Reg cap 256 under (64,4): deep pipeline buffers stay resident.
__global__ void __launch_bounds__(64, 4)
msloss_kernel(const float* __restrict__ pred,
              const float* __restrict__ tgt,
              float* __restrict__ out) {
    const int sp  = blockIdx.x;     // span index within T
    const int b   = blockIdx.y;     // batch index
    const int col = threadIdx.x;    // 0..63, one feature column per thread

    const int tstart = sp * SPAN;
    const int t0     = (sp == 0) ? 0 : (tstart - (WU + 1));

    const size_t base = (size_t)b * Tq * Dq + (size_t)col;
    const float* pp = pred + base + (size_t)t0 * Dq;
    const float* qq = tgt  + base + (size_t)t0 * Dq;

    // seed: ema_0 = x_0 at the seed row
    float xp = *pp, xq = *qq;
    Ema s;
    s.pe0 = s.pe1 = s.pe2 = xp;
    s.te0 = s.te1 = s.te2 = xq;

    float P[4][8], Q[4][8];   // 4-deep rotating prefetch buffers

    if (sp != 0) {
        pp += Dq; qq += Dq;
        // ---- warm-up: 12 batches (96 rows), prefetch distance 3 ----
        load8o(pp, qq,  0, P[0], Q[0]);
        load8o(pp, qq,  8, P[1], Q[1]);
        load8o(pp, qq, 16, P[2], Q[2]);
        pp += 24 * Dq; qq += 24 * Dq;
        #pragma unroll 1
        for (int j = 0; j < 2; ++j) {     // consumes batches 4j..4j+3
            load8o(pp, qq,  0, P[3], Q[3]);
            warm8(P[0], Q[0], s);
            load8o(pp, qq,  8, P[0], Q[0]);
            warm8(P[1], Q[1], s);
            load8o(pp, qq, 16, P[1], Q[1]);
            warm8(P[2], Q[2], s);
            load8o(pp, qq, 24, P[2], Q[2]);
            warm8(P[3], Q[3], s);
            pp += 32 * Dq; qq += 32 * Dq;
        }
        // drain: load batch 11, compute 8..11
        load8o(pp, qq, 0, P[3], Q[3]);
        pp += 8 * Dq; qq += 8 * Dq;
        warm8(P[0], Q[0], s);
        warm8(P[1], Q[1], s);
        warm8(P[2], Q[2], s);
        warm8(P[3], Q[3], s);
    }
    // For sp==0 the pointers still sit at row 0: the first main step
    // reprocesses t=0 with dp=dq=0 -> zero loss contribution, ema stays x_0.

    float a0 = 0.f, a1 = 0.f, a2 = 0.f;

    // ---- main: 64 batches (512 rows), prefetch distance 3 ----
    load8o(pp, qq,  0, P[0], Q[0]);
    load8o(pp, qq,  8, P[1], Q[1]);
    load8o(pp, qq, 16, P[2], Q[2]);
    pp += 24 * Dq; qq += 24 * Dq;
    #pragma unroll 1
    for (int j = 0; j < 15; ++j) {        // consumes batches 4j..4j+3
        load8o(pp, qq,  0, P[3], Q[3]);
        loss8(P[0], Q[0], s, a0, a1, a2);
        load8o(pp, qq,  8, P[0], Q[0]);
        loss8(P[1], Q[1], s, a0, a1, a2);
        load8o(pp, qq, 16, P[1], Q[1]);
        loss8(P[2], Q[2], s, a0, a1, a2);
        load8o(pp, qq, 24, P[2], Q[2]);
        loss8(P[3], Q[3], s, a0, a1, a2);
        pp += 32 * Dq; qq += 32 * Dq;
    }
    // drain: load batch 63, compute 60..63
    load8o(pp, qq, 0, P[3], Q[3]);
    loss8(P[0], Q[0], s, a0, a1, a2);
    loss8(P[1], Q[1], s, a0, a1, a2);
    loss8(P[2], Q[2], s, a0, a1, a2);
    loss8(P[3], Q[3], s, a0, a1, a2);

    float total = 0.5f * a0 + 0.3f * a1 + 0.2f * a2;

    // warp reduce, one atomic per warp
    #pragma unroll
    for (int o = 16; o > 0; o >>= 1)
        total += __shfl_xor_sync(0xFFFFFFFFu, total, o);

    if ((threadIdx.x & 31) == 0) {
        // mean over time (T-1 = 8191) and over B*D (2048)
        atomicAdd(out, total * (1.0f / (8191.0f * 2048.0f)));
    }
}

extern "C" void kernel_launch(void* const* d_in, const int* in_sizes, int n_in,
                              void* d_out, int out_size) {
    const float* pred = (const float*)d_in[0];
    const float* tgt  = (const float*)d_in[1];
    float* out = (float*)d_out;

    zero_out_kernel<<<1, 1>>>(out);
    dim3 grid(NSP, Bq);
    msloss_kernel<<<grid, 64>>>(pred, tgt, out);
}

// round 14
// speedup vs baseline: 1.6228x; 1.6228x over previous
#include <cuda_runtime.h>
#include <cstdint>

typedef unsigned long long ull;

// ---------------- packed f32x2 helpers (sm_103a) ----------------
__device__ __forceinline__ ull f2fma(ull a, ull b, ull c) {
    ull d; asm("fma.rn.f32x2 %0, %1, %2, %3;" : "=l"(d) : "l"(a), "l"(b), "l"(c)); return d;
}
__device__ __forceinline__ ull f2add(ull a, ull b) {
    ull d; asm("add.rn.f32x2 %0, %1, %2;" : "=l"(d) : "l"(a), "l"(b)); return d;
}
__device__ __forceinline__ ull f2mul(ull a, ull b) {
    ull d; asm("mul.rn.f32x2 %0, %1, %2;" : "=l"(d) : "l"(a), "l"(b)); return d;
}
__device__ __forceinline__ ull pack2same(float x) {
    unsigned u = __float_as_uint(x);
    return ((ull)u << 32) | (ull)u;
}

// ---------------- problem constants ----------------
constexpr int Bq  = 32;
constexpr int Tq  = 8192;
constexpr int Dq  = 64;
constexpr int L   = 256;    // timesteps per chunk (loss-accumulating region)
constexpr int WU  = 64;     // warm-up rows after the seed row (history = 65 rows)
constexpr int NCH = Tq / L; // 32 chunks per batch row

struct EmaState {
    ull pe0, pe1, pe2, te0, te1, te2;
};

// dp = x - pe has the same sign as pd = alpha*dp (alpha > 0),
// so the sign-mismatch mask is a sign-bit XOR on dp/dq halves.
__device__ __forceinline__ void step_loss(ull A, ull NEG1, ull x, ull y,
                                          ull& pe, ull& te, ull& acc) {
    ull dp = f2fma(NEG1, pe, x);   // x - pe
    ull dq = f2fma(NEG1, te, y);   // y - te
    pe = f2fma(A, dp, pe);
    te = f2fma(A, dq, te);
    ull df = f2fma(NEG1, te, pe);  // pe_new - te_new
    ull d2 = f2mul(df, df);
    unsigned mlo = (unsigned)(((int)((unsigned)dp         ^ (unsigned)dq))         >> 31);
    unsigned mhi = (unsigned)(((int)((unsigned)(dp >> 32) ^ (unsigned)(dq >> 32))) >> 31);
    unsigned rlo = mlo & (unsigned)d2;
    unsigned rhi = mhi & (unsigned)(d2 >> 32);
    acc = f2add(acc, ((ull)rhi << 32) | (ull)rlo);
}

__device__ __forceinline__ void step_warm(ull A, ull NEG1, ull x, ull y,
                                          ull& pe, ull& te) {
    ull dp = f2fma(NEG1, pe, x);
    ull dq = f2fma(NEG1, te, y);
    pe = f2fma(A, dp, pe);
    te = f2fma(A, dq, te);
}

// Load 8 rows at a compile-time row offset (immediate-offset LDGs).
__device__ __forceinline__ void load8o(const float* pp, const float* qq, int rofs,
                                       ull* P, ull* Q) {
    #pragma unroll
    for (int u = 0; u < 8; ++u) {
        P[u] = *(const ull*)(pp + (rofs + u) * Dq);
        Q[u] = *(const ull*)(qq + (rofs + u) * Dq);
    }
}

__device__ __forceinline__ void warm8(const ull* P, const ull* Q,
                                      ull A0, ull A1, ull A2, ull NEG1,
                                      EmaState& s) {
    #pragma unroll
    for (int u = 0; u < 8; ++u) {
        step_warm(A0, NEG1, P[u], Q[u], s.pe0, s.te0);
        step_warm(A1, NEG1, P[u], Q[u], s.pe1, s.te1);
        step_warm(A2, NEG1, P[u], Q[u], s.pe2, s.te2);
    }
}

__device__ __forceinline__ void loss8(const ull* P, const ull* Q,
                                      ull A0, ull A1, ull A2, ull NEG1,
                                      EmaState& s, ull& a0, ull& a1, ull& a2) {
    #pragma unroll
    for (int u = 0; u < 8; ++u) {
        step_loss(A0, NEG1, P[u], Q[u], s.pe0, s.te0, a0);
        step_loss(A1, NEG1, P[u], Q[u], s.pe1, s.te1, a1);
        step_loss(A2, NEG1, P[u], Q[u], s.pe2, s.te2, a2);
    }
}

__global__ void zero_out_kernel(float* out) { out[0] = 0.0f; }

// min 7 blocks/SM needed for the 1024-CTA single wave; high reg cap keeps
// all 4 pipeline buffers resident instead of letting ptxas collapse them.
__global__ void __launch_bounds__(32, 7)
msloss_kernel(const float* __restrict__ pred,
              const float* __restrict__ tgt,
              float* __restrict__ out) {
    const int c    = blockIdx.x;       // chunk index within T
    const int b    = blockIdx.y;       // batch index
    const int lane = threadIdx.x;      // 0..31, owns columns {2*lane, 2*lane+1}

    const int tstart = c * L;
    const int t0     = (c == 0) ? 0 : (tstart - (WU + 1));

    const size_t colbase = (size_t)b * Tq * Dq + (size_t)2 * lane;
    const float* pp = pred + colbase + (size_t)t0 * Dq;
    const float* qq = tgt  + colbase + (size_t)t0 * Dq;

    const ull A0 = pack2same(0.1f);
    const ull A1 = pack2same(0.3f);
    const ull A2 = pack2same(0.5f);
    const ull NEG1 = pack2same(-1.0f);

    // seed: ema_0 = x_0 at the seed row
    ull xp = *(const ull*)pp;
    ull xq = *(const ull*)qq;
    EmaState s;
    s.pe0 = s.pe1 = s.pe2 = xp;
    s.te0 = s.te1 = s.te2 = xq;

    ull P[4][8], Q[4][8];   // 4-deep rotating prefetch buffers

    if (c != 0) {
        pp += Dq; qq += Dq;
        // ---- warm-up: 8 batches (64 rows), prefetch distance 3 ----
        load8o(pp, qq,  0, P[0], Q[0]);
        load8o(pp, qq,  8, P[1], Q[1]);
        load8o(pp, qq, 16, P[2], Q[2]);
        pp += 24 * Dq; qq += 24 * Dq;
        // one full rotation (batches 0..3)
        load8o(pp, qq,  0, P[3], Q[3]);
        warm8(P[0], Q[0], A0, A1, A2, NEG1, s);
        load8o(pp, qq,  8, P[0], Q[0]);
        warm8(P[1], Q[1], A0, A1, A2, NEG1, s);
        load8o(pp, qq, 16, P[1], Q[1]);
        warm8(P[2], Q[2], A0, A1, A2, NEG1, s);
        load8o(pp, qq, 24, P[2], Q[2]);
        warm8(P[3], Q[3], A0, A1, A2, NEG1, s);
        pp += 32 * Dq; qq += 32 * Dq;
        // drain: load batch 7, compute 4..7
        load8o(pp, qq, 0, P[3], Q[3]);
        pp += 8 * Dq; qq += 8 * Dq;
        warm8(P[0], Q[0], A0, A1, A2, NEG1, s);
        warm8(P[1], Q[1], A0, A1, A2, NEG1, s);
        warm8(P[2], Q[2], A0, A1, A2, NEG1, s);
        warm8(P[3], Q[3], A0, A1, A2, NEG1, s);
    }
    // For c==0 the pointers still sit at row 0: the first main step
    // reprocesses t=0 with dp=dq=0 -> zero loss contribution, ema stays x_0.

    ull acc0 = 0, acc1 = 0, acc2 = 0;

    // ---- main: 32 batches (256 rows), prefetch distance 3 ----
    load8o(pp, qq,  0, P[0], Q[0]);
    load8o(pp, qq,  8, P[1], Q[1]);
    load8o(pp, qq, 16, P[2], Q[2]);
    pp += 24 * Dq; qq += 24 * Dq;
    #pragma unroll 1
    for (int j = 0; j < 7; ++j) {           // consumes batches 4j..4j+3
        load8o(pp, qq,  0, P[3], Q[3]);
        loss8(P[0], Q[0], A0, A1, A2, NEG1, s, acc0, acc1, acc2);
        load8o(pp, qq,  8, P[0], Q[0]);
        loss8(P[1], Q[1], A0, A1, A2, NEG1, s, acc0, acc1, acc2);
        load8o(pp, qq, 16, P[1], Q[1]);
        loss8(P[2], Q[2], A0, A1, A2, NEG1, s, acc0, acc1, acc2);
        load8o(pp, qq, 24, P[2], Q[2]);
        loss8(P[3], Q[3], A0, A1, A2, NEG1, s, acc0, acc1, acc2);
        pp += 32 * Dq; qq += 32 * Dq;
    }
    // drain: load last batch (31), compute 28..31
    load8o(pp, qq, 0, P[3], Q[3]);
    loss8(P[0], Q[0], A0, A1, A2, NEG1, s, acc0, acc1, acc2);
    loss8(P[1], Q[1], A0, A1, A2, NEG1, s, acc0, acc1, acc2);
    loss8(P[2], Q[2], A0, A1, A2, NEG1, s, acc0, acc1, acc2);
    loss8(P[3], Q[3], A0, A1, A2, NEG1, s, acc0, acc1, acc2);

    // combine halves, apply alpha weights
    float s0 = __uint_as_float((unsigned)acc0) + __uint_as_float((unsigned)(acc0 >> 32));
    float s1 = __uint_as_float((unsigned)acc1) + __uint_as_float((unsigned)(acc1 >> 32));
    float s2 = __uint_as_float((unsigned)acc2) + __uint_as_float((unsigned)(acc2 >> 32));
    float total = 0.5f * s0 + 0.3f * s1 + 0.2f * s2;

    // warp reduce
    #pragma unroll
    for (int o = 16; o > 0; o >>= 1)
        total += __shfl_xor_sync(0xFFFFFFFFu, total, o);

    if (lane == 0) {
        // mean over time (T-1 = 8191) and over B*D (2048)
        atomicAdd(out, total * (1.0f / (8191.0f * 2048.0f)));
    }
}

extern "C" void kernel_launch(void* const* d_in, const int* in_sizes, int n_in,
                              void* d_out, int out_size) {
    const float* pred = (const float*)d_in[0];
    const float* tgt  = (const float*)d_in[1];
    float* out = (float*)d_out;

    zero_out_kernel<<<1, 1>>>(out);
    dim3 grid(NCH, Bq);
    msloss_kernel<<<grid, 32>>>(pred, tgt, out);
}